// round 5
// baseline (speedup 1.0000x reference)
#include <cuda_runtime.h>
#include <math.h>

#define Bq 2
#define Dq 256
#define Hq 8
#define Tq 128
#define Fq 64
#define Cq 512
#define TEq 512
#define NDIST 255   // pd in [-127,127]

// ---------------- scratch (device globals; no allocation allowed) ----------
__device__ float    g_tp [Bq * Tq * Cq];        // time projection (B,T,C)
__device__ float    g_lut[NDIST * Cq];          // dist-emb LUT (255,C)
__device__ unsigned g_Bn [Cq * Cq];             // w_out tf32, TRANSPOSED: [n][k]
__device__ float    g_R  [Bq * Tq * Tq * Cq];   // R (B,T,S,C)   67 MB

// ---------------- tf32 / mma helpers ----------------------------------------
__device__ __forceinline__ unsigned f2tf32(float x) {
    unsigned r;
    asm("cvt.rna.tf32.f32 %0, %1;" : "=r"(r) : "f"(x));
    return r;
}

__device__ __forceinline__ void mma8(float c[4],
                                     const unsigned a[4],
                                     unsigned b0, unsigned b1) {
    asm volatile(
        "mma.sync.aligned.m16n8k8.row.col.f32.tf32.tf32.f32 "
        "{%0,%1,%2,%3}, {%4,%5,%6,%7}, {%8,%9}, {%0,%1,%2,%3};"
        : "+f"(c[0]), "+f"(c[1]), "+f"(c[2]), "+f"(c[3])
        : "r"(a[0]), "r"(a[1]), "r"(a[2]), "r"(a[3]), "r"(b0), "r"(b1));
}

__device__ __forceinline__ void ldsm4(unsigned r[4], unsigned addr) {
    asm volatile("ldmatrix.sync.aligned.m8n8.x4.shared.b16 {%0,%1,%2,%3}, [%4];"
                 : "=r"(r[0]), "=r"(r[1]), "=r"(r[2]), "=r"(r[3]) : "r"(addr));
}

__device__ __forceinline__ float silu(float x) {
    return x / (1.0f + __expf(-x));
}

__device__ __forceinline__ void cpa16(void* dst, const void* src) {
    unsigned d = (unsigned)__cvta_generic_to_shared(dst);
    asm volatile("cp.async.cg.shared.global [%0], [%1], 16;" :: "r"(d), "l"(src) : "memory");
}

// ---------------- kernel 1: time_proj = temb @ w_time + b_time -------------
// 64 blocks x 4 bt-rows; 512 threads = one output channel each.
__global__ __launch_bounds__(512) void tp_kernel(const float* __restrict__ temb,
                                                 const float* __restrict__ w_time,
                                                 const float* __restrict__ b_time) {
    __shared__ float st[4][TEq];
    int c   = threadIdx.x;
    int bt0 = blockIdx.x * 4;
    #pragma unroll
    for (int j = 0; j < 4; ++j)
        st[j][c] = temb[(size_t)(bt0 + j) * TEq + c];
    __syncthreads();
    float a0 = b_time[c], a1 = a0, a2 = a0, a3 = a0;
    // re-zero: each row accumulates independently from bias
    a0 = b_time[c]; a1 = b_time[c]; a2 = b_time[c]; a3 = b_time[c];
    #pragma unroll 8
    for (int k = 0; k < TEq; ++k) {
        float w = w_time[(size_t)k * Cq + c];
        a0 += st[0][k] * w;
        a1 += st[1][k] * w;
        a2 += st[2][k] * w;
        a3 += st[3][k] * w;
    }
    g_tp[(size_t)(bt0 + 0) * Cq + c] = a0;
    g_tp[(size_t)(bt0 + 1) * Cq + c] = a1;
    g_tp[(size_t)(bt0 + 2) * Cq + c] = a2;
    g_tp[(size_t)(bt0 + 3) * Cq + c] = a3;
}

// ---------------- kernel 2: dist LUT ---------------------------------------
__global__ void lut_kernel(const float* __restrict__ w_dist,
                           const float* __restrict__ b_dist) {
    int didx = blockIdx.x;         // 0..254
    int c    = threadIdx.x;        // 0..511
    float d  = (float)(didx - (Tq - 1));
    float e0 = log1pf(fmaxf(d, 0.0f));
    float e1 = log1pf(fmaxf(-d, 0.0f));
    float e2 = (didx == (Tq - 1)) ? 1.0f : 0.0f;
    g_lut[didx * Cq + c] = e0 * w_dist[0 * Cq + c]
                         + e1 * w_dist[1 * Cq + c]
                         + e2 * w_dist[2 * Cq + c]
                         + b_dist[c];
}

// ---------------- kernel 2b: w_out -> tf32, transposed to [n][k] ------------
__global__ void cvtB_kernel(const float* __restrict__ w_out) {
    int k = blockIdx.x, n = threadIdx.x;
    g_Bn[(size_t)n * Cq + k]         = f2tf32(w_out[(size_t)k * Cq + n]);
    g_Bn[(size_t)(n + 256) * Cq + k] = f2tf32(w_out[(size_t)k * Cq + n + 256]);
}

// ---------------- kernel 3: R = silu(tp + lut[pd]) @ w_out + b_out ----------
// M=32768, N=512, K=512. Block 128x128, K-chunk 32, double buffer, ldmatrix.
__global__ __launch_bounds__(256) void gemmR_tc(const int* __restrict__ pd,
                                                const float* __restrict__ b_out) {
    __shared__ unsigned As[2][128][36];   // [m][k]
    __shared__ unsigned Bs[2][128][36];   // [n][k]
    __shared__ int   sdid[128];
    __shared__ float stp[512];
    __shared__ float sbo[128];

    const unsigned BUFB = 128 * 36 * 4;   // bytes per buffer

    int tid = threadIdx.x;
    int bn = blockIdx.x;           // 0..3 (N tile)
    int bt = blockIdx.y;           // 0..255 (one (b,t) pair = 128 M rows)

    if (tid < 128) sdid[tid] = pd[bt * 128 + tid] + (Tq - 1);
    stp[tid]       = g_tp[bt * Cq + tid];
    stp[tid + 256] = g_tp[bt * Cq + tid + 256];
    if (tid < 128) sbo[tid] = b_out[bn * 128 + tid];
    __syncthreads();

    // ---- per-thread A-producer geometry: 4 rows, 4 consecutive k each ----
    int k4 = (tid & 7) * 4;
    int sRow[4];
    const float* lrow[4];
    #pragma unroll
    for (int r = 0; r < 4; ++r) {
        sRow[r] = (tid + r * 256) >> 3;
        lrow[r] = g_lut + (size_t)sdid[sRow[r]] * Cq + k4;
    }
    // ---- per-thread B cp.async geometry: Bs[n][seg*4] <- g_Bn[n][k0+seg*4] --
    int bn_row = tid >> 3;         // 0..31 (plus r*32)
    int bseg   = tid & 7;          // 0..7
    const unsigned* Bsrc = g_Bn + (size_t)(bn * 128) * Cq + bseg * 4;

    float4 areg[4];

    // ---- prologue: chunk 0 ----
    #pragma unroll
    for (int r = 0; r < 4; ++r)
        cpa16(&Bs[0][bn_row + 32 * r][bseg * 4],
              Bsrc + (size_t)(bn_row + 32 * r) * Cq);
    asm volatile("cp.async.commit_group;" ::: "memory");
    #pragma unroll
    for (int r = 0; r < 4; ++r) areg[r] = *(const float4*)(lrow[r]);
    #pragma unroll
    for (int r = 0; r < 4; ++r) {
        uint4 o;
        o.x = f2tf32(silu(stp[k4 + 0] + areg[r].x));
        o.y = f2tf32(silu(stp[k4 + 1] + areg[r].y));
        o.z = f2tf32(silu(stp[k4 + 2] + areg[r].z));
        o.w = f2tf32(silu(stp[k4 + 3] + areg[r].w));
        *(uint4*)&As[0][sRow[r]][k4] = o;
    }
    asm volatile("cp.async.wait_group 0;" ::: "memory");
    __syncthreads();

    int lane = tid & 31, warp = tid >> 5;
    int g = lane >> 2, tig = lane & 3;
    int wm = warp >> 1, wn = warp & 1;
    int mbase = wm * 32, nbase = wn * 64;

    // ---- ldmatrix base addresses (buffer 0) ----
    unsigned aBase = (unsigned)__cvta_generic_to_shared(&As[0][0][0]);
    unsigned bBase = (unsigned)__cvta_generic_to_shared(&Bs[0][0][0]);
    int rowA = lane & 15;
    int colA = (lane >> 4) * 4;
    unsigned aAddr[2];
    #pragma unroll
    for (int mt = 0; mt < 2; ++mt)
        aAddr[mt] = aBase + ((mbase + mt * 16 + rowA) * 36 + colA) * 4;
    int rowB = (lane & 7) | ((lane & 16) >> 1);   // 0..15
    int colB = ((lane >> 3) & 1) * 4;
    unsigned bAddr[4];
    #pragma unroll
    for (int p = 0; p < 4; ++p)
        bAddr[p] = bBase + ((nbase + p * 16 + rowB) * 36 + colB) * 4;

    float acc[2][8][4] = {};

    for (int i = 0; i < 16; ++i) {
        int cur = i & 1, nxt = cur ^ 1;
        unsigned bufo = cur * BUFB;
        int k1 = (i + 1) * 32;
        if (i < 15) {
            #pragma unroll
            for (int r = 0; r < 4; ++r)
                cpa16(&Bs[nxt][bn_row + 32 * r][bseg * 4],
                      Bsrc + (size_t)k1 + (size_t)(bn_row + 32 * r) * Cq);
            asm volatile("cp.async.commit_group;" ::: "memory");
            #pragma unroll
            for (int r = 0; r < 4; ++r) areg[r] = *(const float4*)(lrow[r] + k1);
        }
        #pragma unroll
        for (int q = 0; q < 4; ++q) {
            unsigned off = bufo + q * 32;           // q*8 words
            unsigned a0[4], a1[4], bfr[4];
            ldsm4(a0, aAddr[0] + off);
            ldsm4(a1, aAddr[1] + off);
            #pragma unroll
            for (int p = 0; p < 4; ++p) {
                ldsm4(bfr, bAddr[p] + off);
                mma8(acc[0][2 * p],     a0, bfr[0], bfr[1]);
                mma8(acc[0][2 * p + 1], a0, bfr[2], bfr[3]);
                mma8(acc[1][2 * p],     a1, bfr[0], bfr[1]);
                mma8(acc[1][2 * p + 1], a1, bfr[2], bfr[3]);
            }
        }
        if (i < 15) {
            #pragma unroll
            for (int r = 0; r < 4; ++r) {
                uint4 o;
                o.x = f2tf32(silu(stp[k1 + k4 + 0] + areg[r].x));
                o.y = f2tf32(silu(stp[k1 + k4 + 1] + areg[r].y));
                o.z = f2tf32(silu(stp[k1 + k4 + 2] + areg[r].z));
                o.w = f2tf32(silu(stp[k1 + k4 + 3] + areg[r].w));
                *(uint4*)&As[nxt][sRow[r]][k4] = o;
            }
            asm volatile("cp.async.wait_group 0;" ::: "memory");
        }
        __syncthreads();
    }

    // epilogue: R[m][n] = acc + b_out[n]
    size_t Rbase = (size_t)bt * 128 * Cq + bn * 128;
    #pragma unroll
    for (int mt = 0; mt < 2; ++mt) {
        int r0 = mbase + mt * 16 + g;
        #pragma unroll
        for (int nt = 0; nt < 8; ++nt) {
            int nl = nbase + nt * 8 + 2 * tig;
            float2 v0 = make_float2(acc[mt][nt][0] + sbo[nl],
                                    acc[mt][nt][1] + sbo[nl + 1]);
            float2 v1 = make_float2(acc[mt][nt][2] + sbo[nl],
                                    acc[mt][nt][3] + sbo[nl + 1]);
            *(float2*)(g_R + Rbase + (size_t)r0 * Cq + nl)       = v0;
            *(float2*)(g_R + Rbase + (size_t)(r0 + 8) * Cq + nl) = v1;
        }
    }
}

// ---------------- kernel 4: out[b,d,h,t,s] = sum_f qk[b,d,h,t,f]*R[b,t,s,h,f]
__global__ __launch_bounds__(256) void einsum_tc(const float* __restrict__ qk,
                                                 float* __restrict__ out) {
    __shared__ unsigned As[128][68];   // [d][f]
    __shared__ unsigned Bs[128][68];   // [s][f]

    int tid = threadIdx.x;
    int bid = blockIdx.x;              // B*H*T*2 = 4096
    int dchunk = bid & 1; int rest = bid >> 1;
    int t = rest & 127; rest >>= 7;
    int h = rest & 7;   int b = rest >> 3;

    const size_t dstr = (size_t)Hq * Tq * Fq;   // 65536
    const float* qk_base = qk + ((((size_t)b * Dq + dchunk * 128) * Hq + h) * Tq + t) * Fq;
    const float* R_base  = g_R + (size_t)(b * Tq + t) * Tq * Cq + h * Fq;

    #pragma unroll
    for (int r = 0; r < 8; ++r) {
        int idx = tid + r * 256;
        int row = idx >> 4, f4 = (idx & 15) * 4;
        float4 v = *(const float4*)(qk_base + (size_t)row * dstr + f4);
        uint4 o;
        o.x = f2tf32(v.x); o.y = f2tf32(v.y); o.z = f2tf32(v.z); o.w = f2tf32(v.w);
        *(uint4*)&As[row][f4] = o;
    }
    #pragma unroll
    for (int r = 0; r < 8; ++r) {
        int idx = tid + r * 256;
        int row = idx >> 4, f4 = (idx & 15) * 4;
        float4 v = *(const float4*)(R_base + (size_t)row * Cq + f4);
        uint4 o;
        o.x = f2tf32(v.x); o.y = f2tf32(v.y); o.z = f2tf32(v.z); o.w = f2tf32(v.w);
        *(uint4*)&Bs[row][f4] = o;
    }
    __syncthreads();

    int lane = tid & 31, warp = tid >> 5;
    int g = lane >> 2, tig = lane & 3;
    int wm = warp >> 1, wn = warp & 1;
    int mbase = wm * 32, nbase = wn * 64;

    float acc[2][8][4] = {};

    #pragma unroll
    for (int q = 0; q < 8; ++q) {
        int kk = q * 8;
        unsigned a[2][4];
        #pragma unroll
        for (int mt = 0; mt < 2; ++mt) {
            int m = mbase + mt * 16 + g;
            a[mt][0] = As[m][kk + tig];
            a[mt][1] = As[m + 8][kk + tig];
            a[mt][2] = As[m][kk + tig + 4];
            a[mt][3] = As[m + 8][kk + tig + 4];
        }
        #pragma unroll
        for (int nt = 0; nt < 8; ++nt) {
            int n = nbase + nt * 8 + g;
            unsigned b0 = Bs[n][kk + tig];
            unsigned b1 = Bs[n][kk + tig + 4];
            mma8(acc[0][nt], a[0], b0, b1);
            mma8(acc[1][nt], a[1], b0, b1);
        }
    }

    const size_t ostr = (size_t)Hq * Tq * Tq;   // 131072
    float* out_base = out + ((((size_t)b * Dq + dchunk * 128) * Hq + h) * Tq + t) * Tq;
    #pragma unroll
    for (int mt = 0; mt < 2; ++mt) {
        int r0 = mbase + mt * 16 + g;
        #pragma unroll
        for (int nt = 0; nt < 8; ++nt) {
            int nl = nbase + nt * 8 + 2 * tig;
            *(float2*)(out_base + (size_t)r0 * ostr + nl) =
                make_float2(acc[mt][nt][0], acc[mt][nt][1]);
            *(float2*)(out_base + (size_t)(r0 + 8) * ostr + nl) =
                make_float2(acc[mt][nt][2], acc[mt][nt][3]);
        }
    }
}

// ---------------------------------------------------------------------------
extern "C" void kernel_launch(void* const* d_in, const int* in_sizes, int n_in,
                              void* d_out, int out_size) {
    const float* qk     = (const float*)d_in[0];
    const float* temb   = (const float*)d_in[1];
    const int*   pd     = (const int*)  d_in[2];
    const float* w_dist = (const float*)d_in[3];
    const float* b_dist = (const float*)d_in[4];
    const float* w_time = (const float*)d_in[5];
    const float* b_time = (const float*)d_in[6];
    const float* w_out  = (const float*)d_in[7];
    const float* b_out  = (const float*)d_in[8];
    float* out = (float*)d_out;

    tp_kernel <<<Bq * Tq / 4, 512>>>(temb, w_time, b_time);
    lut_kernel<<<NDIST, Cq>>>(w_dist, b_dist);
    cvtB_kernel<<<Cq, 256>>>(w_out);
    dim3 gR(Cq / 128, (Bq * Tq * Tq) / 128);
    gemmR_tc<<<gR, 256>>>(pd, b_out);
    einsum_tc<<<Bq * Hq * Tq * 2, 256>>>(qk, out);
}

// round 6
// speedup vs baseline: 1.1436x; 1.1436x over previous
#include <cuda_runtime.h>
#include <math.h>

#define Bq 2
#define Dq 256
#define Hq 8
#define Tq 128
#define Fq 64
#define Cq 512
#define TEq 512
#define NDIST 255   // pd in [-127,127]

// ---------------- scratch (device globals; no allocation allowed) ----------
__device__ float    g_tp [Bq * Tq * Cq];        // time projection (B,T,C)
__device__ float    g_lut[NDIST * Cq];          // dist-emb LUT (255,C)
__device__ unsigned g_Bn [Cq * Cq];             // w_out tf32, transposed [n][k]
__device__ unsigned g_A  [Bq * Tq * Tq * Cq];   // tf32(silu(emb))  67 MB
__device__ float    g_R  [Bq * Tq * Tq * Cq];   // R (B,T,S,C)      67 MB

// ---------------- tf32 / mma helpers ----------------------------------------
__device__ __forceinline__ unsigned f2tf32(float x) {
    unsigned r;
    asm("cvt.rna.tf32.f32 %0, %1;" : "=r"(r) : "f"(x));
    return r;
}

__device__ __forceinline__ void mma8(float c[4],
                                     const unsigned a[4],
                                     unsigned b0, unsigned b1) {
    asm volatile(
        "mma.sync.aligned.m16n8k8.row.col.f32.tf32.tf32.f32 "
        "{%0,%1,%2,%3}, {%4,%5,%6,%7}, {%8,%9}, {%0,%1,%2,%3};"
        : "+f"(c[0]), "+f"(c[1]), "+f"(c[2]), "+f"(c[3])
        : "r"(a[0]), "r"(a[1]), "r"(a[2]), "r"(a[3]), "r"(b0), "r"(b1));
}

__device__ __forceinline__ void ldsm4(unsigned r[4], unsigned addr) {
    asm volatile("ldmatrix.sync.aligned.m8n8.x4.shared.b16 {%0,%1,%2,%3}, [%4];"
                 : "=r"(r[0]), "=r"(r[1]), "=r"(r[2]), "=r"(r[3]) : "r"(addr));
}

__device__ __forceinline__ float silu(float x) {
    return x / (1.0f + __expf(-x));
}

__device__ __forceinline__ void cpa16(void* dst, const void* src) {
    unsigned d = (unsigned)__cvta_generic_to_shared(dst);
    asm volatile("cp.async.cg.shared.global [%0], [%1], 16;" :: "r"(d), "l"(src) : "memory");
}

// ---------------- kernel 1: time_proj = temb @ w_time + b_time -------------
__global__ __launch_bounds__(512) void tp_kernel(const float* __restrict__ temb,
                                                 const float* __restrict__ w_time,
                                                 const float* __restrict__ b_time) {
    __shared__ float st[4][TEq];
    int c   = threadIdx.x;
    int bt0 = blockIdx.x * 4;
    #pragma unroll
    for (int j = 0; j < 4; ++j)
        st[j][c] = temb[(size_t)(bt0 + j) * TEq + c];
    __syncthreads();
    float a0 = b_time[c], a1 = a0, a2 = a0, a3 = a0;
    #pragma unroll 8
    for (int k = 0; k < TEq; ++k) {
        float w = w_time[(size_t)k * Cq + c];
        a0 += st[0][k] * w;
        a1 += st[1][k] * w;
        a2 += st[2][k] * w;
        a3 += st[3][k] * w;
    }
    g_tp[(size_t)(bt0 + 0) * Cq + c] = a0;
    g_tp[(size_t)(bt0 + 1) * Cq + c] = a1;
    g_tp[(size_t)(bt0 + 2) * Cq + c] = a2;
    g_tp[(size_t)(bt0 + 3) * Cq + c] = a3;
}

// ---------------- kernel 2: dist LUT ---------------------------------------
__global__ void lut_kernel(const float* __restrict__ w_dist,
                           const float* __restrict__ b_dist) {
    int didx = blockIdx.x;         // 0..254
    int c    = threadIdx.x;        // 0..511
    float d  = (float)(didx - (Tq - 1));
    float e0 = log1pf(fmaxf(d, 0.0f));
    float e1 = log1pf(fmaxf(-d, 0.0f));
    float e2 = (didx == (Tq - 1)) ? 1.0f : 0.0f;
    g_lut[didx * Cq + c] = e0 * w_dist[0 * Cq + c]
                         + e1 * w_dist[1 * Cq + c]
                         + e2 * w_dist[2 * Cq + c]
                         + b_dist[c];
}

// ---------------- kernel 2b: w_out -> tf32, transposed to [n][k] ------------
__global__ void cvtB_kernel(const float* __restrict__ w_out) {
    int k = blockIdx.x, n = threadIdx.x;
    g_Bn[(size_t)n * Cq + k]         = f2tf32(w_out[(size_t)k * Cq + n]);
    g_Bn[(size_t)(n + 256) * Cq + k] = f2tf32(w_out[(size_t)k * Cq + n + 256]);
}

// ---------------- kernel 2c: A = tf32(silu(tp + lut[pd]))  -------------------
// one thread = one float4 segment of one (b,t,s) row; warp shares one row.
__global__ __launch_bounds__(256) void act_kernel(const int* __restrict__ pd) {
    int idx    = blockIdx.x * 256 + threadIdx.x;
    int k4     = (idx & 127) * 4;          // 0..508
    int rowidx = idx >> 7;                 // 0..32767  (= bt*128 + s)
    int bt     = rowidx >> 7;
    int didx   = pd[rowidx] + (Tq - 1);
    float4 l = *(const float4*)(g_lut + (size_t)didx * Cq + k4);
    float4 t = *(const float4*)(g_tp  + (size_t)bt   * Cq + k4);
    uint4 o;
    o.x = f2tf32(silu(t.x + l.x));
    o.y = f2tf32(silu(t.y + l.y));
    o.z = f2tf32(silu(t.z + l.z));
    o.w = f2tf32(silu(t.w + l.w));
    *(uint4*)(g_A + (size_t)rowidx * Cq + k4) = o;
}

// ---------------- kernel 3: R = A @ w_out^T + b_out  (pure tf32 GEMM) -------
// M=32768, N=512, K=512. Block 128x128, K-chunk 32, 3-stage cp.async pipeline.
__global__ __launch_bounds__(256) void gemmR_tc(const float* __restrict__ b_out) {
    __shared__ unsigned As[3][128][36];   // [m][k]
    __shared__ unsigned Bs[3][128][36];   // [n][k]
    __shared__ float sbo[128];

    const unsigned BUFB = 128 * 36 * 4;   // bytes per stage

    int tid = threadIdx.x;
    int bn = blockIdx.x;           // 0..3
    int bt = blockIdx.y;           // 0..255
    if (tid < 128) sbo[tid] = b_out[bn * 128 + tid];

    // cp.async geometry: 128 rows x 8 segs per operand -> 4 segs/thread each
    int rrow = tid >> 3;           // 0..31 (+32*r)
    int seg  = tid & 7;            // 0..7
    const unsigned* Asrc = g_A  + (size_t)(bt * 128) * Cq + seg * 4;
    const unsigned* Bsrc = g_Bn + (size_t)(bn * 128) * Cq + seg * 4;

    #define ISSUE(stage, kk)                                                   \
        { _Pragma("unroll")                                                    \
          for (int r = 0; r < 4; ++r) {                                        \
              cpa16(&As[stage][rrow + 32 * r][seg * 4],                        \
                    Asrc + (size_t)(kk) + (size_t)(rrow + 32 * r) * Cq);       \
              cpa16(&Bs[stage][rrow + 32 * r][seg * 4],                        \
                    Bsrc + (size_t)(kk) + (size_t)(rrow + 32 * r) * Cq);       \
          }                                                                    \
          asm volatile("cp.async.commit_group;" ::: "memory"); }

    // prologue: chunks 0 and 1
    ISSUE(0, 0)
    ISSUE(1, 32)
    asm volatile("cp.async.wait_group 1;" ::: "memory");
    __syncthreads();

    int lane = tid & 31, warp = tid >> 5;
    int g = lane >> 2, tig = lane & 3;
    int wm = warp >> 1, wn = warp & 1;
    int mbase = wm * 32, nbase = wn * 64;

    unsigned aBase = (unsigned)__cvta_generic_to_shared(&As[0][0][0]);
    unsigned bBase = (unsigned)__cvta_generic_to_shared(&Bs[0][0][0]);
    int rowA = lane & 15;
    int colA = (lane >> 4) * 4;
    unsigned aAddr[2];
    #pragma unroll
    for (int mt = 0; mt < 2; ++mt)
        aAddr[mt] = aBase + ((mbase + mt * 16 + rowA) * 36 + colA) * 4;
    int rowB = (lane & 7) | ((lane & 16) >> 1);
    int colB = ((lane >> 3) & 1) * 4;
    unsigned bAddr[4];
    #pragma unroll
    for (int p = 0; p < 4; ++p)
        bAddr[p] = bBase + ((nbase + p * 16 + rowB) * 36 + colB) * 4;

    float acc[2][8][4] = {};

    for (int i = 0; i < 16; ++i) {
        int cur = i % 3;
        if (i + 2 < 16) ISSUE((i + 2) % 3, (i + 2) * 32)
        unsigned bufo = (unsigned)cur * BUFB;
        #pragma unroll
        for (int q = 0; q < 4; ++q) {
            unsigned off = bufo + q * 32;
            unsigned a0[4], a1[4], bfr[4];
            ldsm4(a0, aAddr[0] + off);
            ldsm4(a1, aAddr[1] + off);
            #pragma unroll
            for (int p = 0; p < 4; ++p) {
                ldsm4(bfr, bAddr[p] + off);
                mma8(acc[0][2 * p],     a0, bfr[0], bfr[1]);
                mma8(acc[0][2 * p + 1], a0, bfr[2], bfr[3]);
                mma8(acc[1][2 * p],     a1, bfr[0], bfr[1]);
                mma8(acc[1][2 * p + 1], a1, bfr[2], bfr[3]);
            }
        }
        if (i < 15) {
            if (i + 2 < 16)
                asm volatile("cp.async.wait_group 1;" ::: "memory");
            else
                asm volatile("cp.async.wait_group 0;" ::: "memory");
            __syncthreads();
        }
    }
    #undef ISSUE

    // epilogue: R[m][n] = acc + b_out[n]
    size_t Rbase = (size_t)bt * 128 * Cq + bn * 128;
    #pragma unroll
    for (int mt = 0; mt < 2; ++mt) {
        int r0 = mbase + mt * 16 + g;
        #pragma unroll
        for (int nt = 0; nt < 8; ++nt) {
            int nl = nbase + nt * 8 + 2 * tig;
            float2 v0 = make_float2(acc[mt][nt][0] + sbo[nl],
                                    acc[mt][nt][1] + sbo[nl + 1]);
            float2 v1 = make_float2(acc[mt][nt][2] + sbo[nl],
                                    acc[mt][nt][3] + sbo[nl + 1]);
            *(float2*)(g_R + Rbase + (size_t)r0 * Cq + nl)       = v0;
            *(float2*)(g_R + Rbase + (size_t)(r0 + 8) * Cq + nl) = v1;
        }
    }
}

// ---------------- kernel 4: out[b,d,h,t,s] = sum_f qk[b,d,h,t,f]*R[b,t,s,h,f]
__global__ __launch_bounds__(256) void einsum_tc(const float* __restrict__ qk,
                                                 float* __restrict__ out) {
    __shared__ unsigned As[128][68];   // [d][f]
    __shared__ unsigned Bs[128][68];   // [s][f]

    int tid = threadIdx.x;
    int bid = blockIdx.x;              // B*H*T*2 = 4096
    int dchunk = bid & 1; int rest = bid >> 1;
    int t = rest & 127; rest >>= 7;
    int h = rest & 7;   int b = rest >> 3;

    const size_t dstr = (size_t)Hq * Tq * Fq;   // 65536
    const float* qk_base = qk + ((((size_t)b * Dq + dchunk * 128) * Hq + h) * Tq + t) * Fq;
    const float* R_base  = g_R + (size_t)(b * Tq + t) * Tq * Cq + h * Fq;

    #pragma unroll
    for (int r = 0; r < 8; ++r) {
        int idx = tid + r * 256;
        int row = idx >> 4, f4 = (idx & 15) * 4;
        float4 v = *(const float4*)(qk_base + (size_t)row * dstr + f4);
        uint4 o;
        o.x = f2tf32(v.x); o.y = f2tf32(v.y); o.z = f2tf32(v.z); o.w = f2tf32(v.w);
        *(uint4*)&As[row][f4] = o;
    }
    #pragma unroll
    for (int r = 0; r < 8; ++r) {
        int idx = tid + r * 256;
        int row = idx >> 4, f4 = (idx & 15) * 4;
        float4 v = *(const float4*)(R_base + (size_t)row * Cq + f4);
        uint4 o;
        o.x = f2tf32(v.x); o.y = f2tf32(v.y); o.z = f2tf32(v.z); o.w = f2tf32(v.w);
        *(uint4*)&Bs[row][f4] = o;
    }
    __syncthreads();

    int lane = tid & 31, warp = tid >> 5;
    int g = lane >> 2, tig = lane & 3;
    int wm = warp >> 1, wn = warp & 1;
    int mbase = wm * 32, nbase = wn * 64;

    float acc[2][8][4] = {};

    #pragma unroll
    for (int q = 0; q < 8; ++q) {
        int kk = q * 8;
        unsigned a[2][4];
        #pragma unroll
        for (int mt = 0; mt < 2; ++mt) {
            int m = mbase + mt * 16 + g;
            a[mt][0] = As[m][kk + tig];
            a[mt][1] = As[m + 8][kk + tig];
            a[mt][2] = As[m][kk + tig + 4];
            a[mt][3] = As[m + 8][kk + tig + 4];
        }
        #pragma unroll
        for (int nt = 0; nt < 8; ++nt) {
            int n = nbase + nt * 8 + g;
            unsigned b0 = Bs[n][kk + tig];
            unsigned b1 = Bs[n][kk + tig + 4];
            mma8(acc[0][nt], a[0], b0, b1);
            mma8(acc[1][nt], a[1], b0, b1);
        }
    }

    const size_t ostr = (size_t)Hq * Tq * Tq;   // 131072
    float* out_base = out + ((((size_t)b * Dq + dchunk * 128) * Hq + h) * Tq + t) * Tq;
    #pragma unroll
    for (int mt = 0; mt < 2; ++mt) {
        int r0 = mbase + mt * 16 + g;
        #pragma unroll
        for (int nt = 0; nt < 8; ++nt) {
            int nl = nbase + nt * 8 + 2 * tig;
            *(float2*)(out_base + (size_t)r0 * ostr + nl) =
                make_float2(acc[mt][nt][0], acc[mt][nt][1]);
            *(float2*)(out_base + (size_t)(r0 + 8) * ostr + nl) =
                make_float2(acc[mt][nt][2], acc[mt][nt][3]);
        }
    }
}

// ---------------------------------------------------------------------------
extern "C" void kernel_launch(void* const* d_in, const int* in_sizes, int n_in,
                              void* d_out, int out_size) {
    const float* qk     = (const float*)d_in[0];
    const float* temb   = (const float*)d_in[1];
    const int*   pd     = (const int*)  d_in[2];
    const float* w_dist = (const float*)d_in[3];
    const float* b_dist = (const float*)d_in[4];
    const float* w_time = (const float*)d_in[5];
    const float* b_time = (const float*)d_in[6];
    const float* w_out  = (const float*)d_in[7];
    const float* b_out  = (const float*)d_in[8];
    float* out = (float*)d_out;

    tp_kernel <<<Bq * Tq / 4, 512>>>(temb, w_time, b_time);
    lut_kernel<<<NDIST, Cq>>>(w_dist, b_dist);
    cvtB_kernel<<<Cq, 256>>>(w_out);
    act_kernel<<<(Bq * Tq * Tq * Cq / 4) / 256, 256>>>(pd);
    dim3 gR(Cq / 128, (Bq * Tq * Tq) / 128);
    gemmR_tc<<<gR, 256>>>(b_out);
    einsum_tc<<<Bq * Hq * Tq * 2, 256>>>(qk, out);
}